// round 14
// baseline (speedup 1.0000x reference)
#include <cuda_runtime.h>
#include <math_constants.h>

// MaxPlusDense: out[b,u] = max( max_i (x[b,i] - kernel[i,u]), bias[u] )
// B=256, D=1024, U=1024, fp32.
//
// R12 skeleton (best measured structure: issue 62.5%) with ONE change:
// SPLITS 8 -> 16. Grid 2048 CTAs -> 8 resident CTAs/SM (reg-limited),
// 4 warps/SMSP (2x R12) to cover LDS latency. Everything else identical.

#define B_DIM 256
#define D_DIM 1024
#define U_DIM 1024

#define SPLITS 16
#define KSEG   (D_DIM / SPLITS)   // 64
#define BM 64
#define BN 32
#define BK 16
#define NT 64
#define NTILES ((B_DIM / BM) * (U_DIM / BN))   // 128

__device__ float    g_scratch[SPLITS][B_DIM * U_DIM];   // 16 MB partials
__device__ unsigned g_cnt[NTILES];                      // monotonic counters

__device__ __forceinline__ unsigned atom_add_acqrel(unsigned* p, unsigned v) {
    unsigned old;
    asm volatile("atom.acq_rel.gpu.global.add.u32 %0, [%1], %2;"
                 : "=r"(old) : "l"(p), "r"(v) : "memory");
    return old;
}

// one k-step contribution of A-component `ac` into accumulator row Q
#define MP_ROW(Q, ac)                        \
    Q.x = fmaxf(Q.x, (ac) - Bv.x);           \
    Q.y = fmaxf(Q.y, (ac) - Bv.y);           \
    Q.z = fmaxf(Q.z, (ac) - Bv.z);           \
    Q.w = fmaxf(Q.w, (ac) - Bv.w);

__global__ __launch_bounds__(NT, 8) void maxplus_fused(
    const float* __restrict__ X,     // (B, D)
    const float* __restrict__ W,     // (D, U)
    const float* __restrict__ bias,  // (U,)
    float* __restrict__ out)         // (B, U)
{
    __shared__ __align__(16) float xs[BK][BM + 4];   // x^T tile: xs[k][m], pitch 68
    __shared__ __align__(16) float ws[BK][BN + 4];   // W tile:   ws[k][n], pitch 36
    __shared__ int s_last;

    const int tid   = threadIdx.x;
    const int lane  = tid & 31;
    const int wid   = tid >> 5;           // 0..1
    const int bn    = blockIdx.x * BN;
    const int bm    = blockIdx.y * BM;
    const int split = blockIdx.z;
    const int kbase = split * KSEG;

    // warp tile 32(m) x 32(n); lane = 4(r) x 8(c); microtile 8m x 4n
    const int wb = wid * 32;              // warp m-base
    const int r4 = (lane & 3) * 4;        // 0,4,8,12
    const int c4 = (lane >> 2) * 4;       // 0..28

    // ---- staging maps ----
    // X: 4 float4/thread: rows xm, xm+32; k-quads x4, x4+8
    const int xm = tid >> 1;              // 0..31
    const int x4 = (tid & 1) * 4;         // 0 or 4
    // W: 2 float4/thread: k-rows wk, wk+8; n-quad wn
    const int wk = tid >> 3;              // 0..7
    const int wn = (tid & 7) * 4;         // 0..28

    const float* xg = X + (size_t)(bm + xm) * D_DIM + kbase + x4;
    const float* wg = W + (size_t)(kbase + wk) * U_DIM + bn + wn;

    float4 q0, q1, q2, q3, q4, q5, q6, q7;
    q0 = q1 = q2 = q3 = q4 = q5 = q6 = q7 =
        make_float4(-CUDART_INF_F, -CUDART_INF_F, -CUDART_INF_F, -CUDART_INF_F);

    // prologue: stage tile 0 in registers
    float4 xv00, xv01, xv10, xv11, wv0, wv1;
    xv00 = *(const float4*)(xg);                                   // (xm,    x4)
    xv01 = *(const float4*)(xg + 8);                               // (xm,    x4+8)
    xv10 = *(const float4*)(xg + (size_t)32 * D_DIM);              // (xm+32, x4)
    xv11 = *(const float4*)(xg + (size_t)32 * D_DIM + 8);          // (xm+32, x4+8)
    wv0  = *(const float4*)(wg);
    wv1  = *(const float4*)(wg + (size_t)8 * U_DIM);

#pragma unroll 1
    for (int t = 0; t < KSEG / BK; t++) {
        // ---- commit staged regs to smem (X transposed; conflict-free STS) ----
        xs[x4 + 0][xm] = xv00.x;  xs[x4 + 1][xm] = xv00.y;
        xs[x4 + 2][xm] = xv00.z;  xs[x4 + 3][xm] = xv00.w;
        xs[x4 + 8][xm] = xv01.x;  xs[x4 + 9][xm] = xv01.y;
        xs[x4 + 10][xm] = xv01.z; xs[x4 + 11][xm] = xv01.w;
        xs[x4 + 0][xm + 32] = xv10.x;  xs[x4 + 1][xm + 32] = xv10.y;
        xs[x4 + 2][xm + 32] = xv10.z;  xs[x4 + 3][xm + 32] = xv10.w;
        xs[x4 + 8][xm + 32] = xv11.x;  xs[x4 + 9][xm + 32] = xv11.y;
        xs[x4 + 10][xm + 32] = xv11.z; xs[x4 + 11][xm + 32] = xv11.w;
        *(float4*)&ws[wk][wn]     = wv0;
        *(float4*)&ws[wk + 8][wn] = wv1;
        __syncthreads();

        // ---- prefetch next tile (L2-resident) ----
        if (t + 1 < KSEG / BK) {
            const int ko = (t + 1) * BK;
            xv00 = *(const float4*)(xg + ko);
            xv01 = *(const float4*)(xg + ko + 8);
            xv10 = *(const float4*)(xg + ko + (size_t)32 * D_DIM);
            xv11 = *(const float4*)(xg + ko + (size_t)32 * D_DIM + 8);
            wv0  = *(const float4*)(wg + (size_t)ko * U_DIM);
            wv1  = *(const float4*)(wg + (size_t)(ko + 8) * U_DIM);
        }

        // ---- compute: 16 k-steps, direct components only ----
#pragma unroll
        for (int kk = 0; kk < BK; kk++) {
            const float4 A0 = *(const float4*)&xs[kk][wb + r4];        // rows 0-3
            const float4 A1 = *(const float4*)&xs[kk][wb + 16 + r4];   // rows 4-7
            const float4 Bv = *(const float4*)&ws[kk][c4];             // cols 0-3
            MP_ROW(q0, A0.x)
            MP_ROW(q1, A0.y)
            MP_ROW(q2, A0.z)
            MP_ROW(q3, A0.w)
            MP_ROW(q4, A1.x)
            MP_ROW(q5, A1.y)
            MP_ROW(q6, A1.z)
            MP_ROW(q7, A1.w)
        }
        __syncthreads();
    }

    // ---- write split partials ----
    {
        float* dst = g_scratch[split];
        const size_t base0 = (size_t)(bm + wb + r4) * U_DIM + bn + c4;
        const size_t base1 = (size_t)(bm + wb + 16 + r4) * U_DIM + bn + c4;
        *(float4*)&dst[base0]               = q0;
        *(float4*)&dst[base0 + U_DIM]       = q1;
        *(float4*)&dst[base0 + 2 * U_DIM]   = q2;
        *(float4*)&dst[base0 + 3 * U_DIM]   = q3;
        *(float4*)&dst[base1]               = q4;
        *(float4*)&dst[base1 + U_DIM]       = q5;
        *(float4*)&dst[base1 + 2 * U_DIM]   = q6;
        *(float4*)&dst[base1 + 3 * U_DIM]   = q7;
    }
    __syncthreads();   // partial STGs happen-before tid0's release-atom

    // ---- last-arriving split reduces this tile ----
    if (tid == 0) {
        unsigned old = atom_add_acqrel(&g_cnt[blockIdx.y * (U_DIM / BN) + blockIdx.x], 1u);
        s_last = (((old + 1) & (SPLITS - 1)) == 0) ? 1 : 0;
    }
    __syncthreads();   // tid0's acquire happens-before all threads' reads

    if (s_last) {
        const float4 bv = *(const float4*)&bias[bn + c4];
#pragma unroll
        for (int half = 0; half < 2; half++) {
            const int rowb = wb + half * 16 + r4;
#pragma unroll
            for (int i = 0; i < 4; i++) {
                const size_t off = (size_t)(bm + rowb + i) * U_DIM + bn + c4;
                float r0 = bv.x, r1 = bv.y, r2 = bv.z, r3 = bv.w;
#pragma unroll
                for (int s = 0; s < SPLITS; s++) {
                    const float4 p = __ldcg((const float4*)&g_scratch[s][off]);
                    r0 = fmaxf(r0, p.x);
                    r1 = fmaxf(r1, p.y);
                    r2 = fmaxf(r2, p.z);
                    r3 = fmaxf(r3, p.w);
                }
                *(float4*)&out[off] = make_float4(r0, r1, r2, r3);
            }
        }
    }
}

extern "C" void kernel_launch(void* const* d_in, const int* in_sizes, int n_in,
                              void* d_out, int out_size)
{
    const float* x      = (const float*)d_in[0];   // (256, 1024)
    const float* kernel = (const float*)d_in[1];   // (1024, 1024)
    const float* bias   = (const float*)d_in[2];   // (1024,)
    float* out          = (float*)d_out;           // (256, 1024)

    dim3 grid(U_DIM / BN, B_DIM / BM, SPLITS);     // (32, 4, 16) = 2048 CTAs
    maxplus_fused<<<grid, NT>>>(x, kernel, bias, out);
}

// round 16
// speedup vs baseline: 1.1998x; 1.1998x over previous
#include <cuda_runtime.h>
#include <math_constants.h>

// MaxPlusDense: out[b,u] = max( max_i (x[b,i] - kernel[i,u]), bias[u] )
// B=256, D=1024, U=1024, fp32.
//
// Bench-optimal single-wave shape (grid 128, warm-L2 graph replay) = R2
// skeleton with:
//   double-buffered smem, ONE barrier per tile (32 total; R2 had 64)
//   bias-initialized accumulators -> epilogue is a bare store
//   register-staged prefetch overlapping the full 32-k compute window
// 26.1 KB static smem (fits 48 KB limit). No split-K, no scratch, no atomics.

#define B_DIM 256
#define D_DIM 1024
#define U_DIM 1024

#define BM 32
#define BN 64
#define BK 32
#define NT 256
#define NTILE (D_DIM / BK)     // 32

#define XPITCH (BM + 2)        // 34
#define WPITCH (BN + 4)        // 68 (float4-aligned rows)

__global__ __launch_bounds__(NT, 1) void maxplus_kernel(
    const float* __restrict__ X,     // (B, D)
    const float* __restrict__ W,     // (D, U)
    const float* __restrict__ bias,  // (U,)
    float* __restrict__ out)         // (B, U)
{
    __shared__ float xs[2][BK][XPITCH];   // x^T tiles: xs[buf][k][m]   (8.7 KB)
    __shared__ float ws[2][BK][WPITCH];   // W tiles:   ws[buf][k][n]   (17.4 KB)

    const int tid = threadIdx.x;
    const int bn  = blockIdx.x * BN;
    const int bm  = blockIdx.y * BM;

    // microtile: 2 rows (m) x 4 cols (n)  [R2 fragment maps: 1wf A, 1wf B]
    const int tm = (tid & 15) * 2;     // 0..30
    const int tn = (tid >> 4) * 4;     // 0..60

    // staging maps (R2-proven)
    const int xr = tid >> 3;           // 0..31 : m
    const int xc = (tid & 7) * 4;      // 0..28 : k quad
    const int wr = tid >> 4;           // 0..15 : k row (+16)
    const int wc = (tid & 15) * 4;     // 0..60 : n quad

    const float* xg = X + (size_t)(bm + xr) * D_DIM + xc;
    const float* wg = W + (size_t)wr * U_DIM + bn + wc;

    // bias-initialized accumulators
    const float4 bv = *(const float4*)&bias[bn + tn];
    float4 q0 = bv, q1 = bv;

    // prologue: stage tile 0 in registers
    float4 xv, wv0, wv1;
    xv  = *(const float4*)(xg);
    wv0 = *(const float4*)(wg);
    wv1 = *(const float4*)(wg + (size_t)16 * U_DIM);

#pragma unroll 1
    for (int t = 0; t < NTILE; t++) {
        const int cur = t & 1;

        // ---- commit staged regs to smem buffer `cur` ----
        xs[cur][xc + 0][xr] = xv.x;
        xs[cur][xc + 1][xr] = xv.y;
        xs[cur][xc + 2][xr] = xv.z;
        xs[cur][xc + 3][xr] = xv.w;
        *(float4*)&ws[cur][wr     ][wc] = wv0;
        *(float4*)&ws[cur][wr + 16][wc] = wv1;
        __syncthreads();   // the only barrier per tile

        // ---- prefetch tile t+1 (L2-resident); hidden by 32-k compute ----
        if (t + 1 < NTILE) {
            const int kb = (t + 1) * BK;
            xv  = *(const float4*)(xg + kb);
            wv0 = *(const float4*)(wg + (size_t)kb * U_DIM);
            wv1 = *(const float4*)(wg + (size_t)(kb + 16) * U_DIM);
        }

        // ---- compute 32 k-steps from buffer `cur` ----
#pragma unroll
        for (int kk = 0; kk < BK; kk++) {
            const float2 a = *(const float2*)&xs[cur][kk][tm];
            const float4 b = *(const float4*)&ws[cur][kk][tn];
            q0.x = fmaxf(q0.x, a.x - b.x);
            q0.y = fmaxf(q0.y, a.x - b.y);
            q0.z = fmaxf(q0.z, a.x - b.z);
            q0.w = fmaxf(q0.w, a.x - b.w);
            q1.x = fmaxf(q1.x, a.y - b.x);
            q1.y = fmaxf(q1.y, a.y - b.y);
            q1.z = fmaxf(q1.z, a.y - b.z);
            q1.w = fmaxf(q1.w, a.y - b.w);
        }
        // no trailing barrier: next iteration stores into the other buffer,
        // and its sync orders buffer reuse (compute(t) precedes STS(t+1)
        // precedes sync(t+1) in every warp's program order).
    }

    // ---- epilogue: bare stores (bias folded into init) ----
    *(float4*)&out[(size_t)(bm + tm    ) * U_DIM + bn + tn] = q0;
    *(float4*)&out[(size_t)(bm + tm + 1) * U_DIM + bn + tn] = q1;
}

extern "C" void kernel_launch(void* const* d_in, const int* in_sizes, int n_in,
                              void* d_out, int out_size)
{
    const float* x      = (const float*)d_in[0];   // (256, 1024)
    const float* kernel = (const float*)d_in[1];   // (1024, 1024)
    const float* bias   = (const float*)d_in[2];   // (1024,)
    float* out          = (float*)d_out;           // (256, 1024)

    dim3 grid(U_DIM / BN, B_DIM / BM);   // (16, 8) = 128 CTAs, single wave
    maxplus_kernel<<<grid, NT>>>(x, kernel, bias, out);
}